// round 4
// baseline (speedup 1.0000x reference)
#include <cuda_runtime.h>
#include <cstdint>

#define Bsz 64
#define Ssz 2048
#define Isz 512
#define Hsz 512

// ============================================================
// Phase 1: xW = x @ W + b   (M=131072, K=512, N=512)
// 128x128 block tile, BK=8, 256 threads, 8x8 thread tile,
// packed f32x2 FMA. 2 CTAs/SM to hide sync bubbles.
// ============================================================
__global__ __launch_bounds__(256, 2) void sgemm_xw(
    const float* __restrict__ A,    // [M,512] = x
    const float* __restrict__ Wm,   // [512,512] = W_i  (row-major [K][N])
    const float* __restrict__ bias, // [512]
    float* __restrict__ C)          // [M,512] = xW+b (hidden region of d_out)
{
    constexpr int K = 512, N = 512;
    __shared__ float As[8][128];
    __shared__ float Bs[8][128];

    const int tid  = threadIdx.x;
    const int bm   = blockIdx.y, bn = blockIdx.x;
    const int arow = tid >> 1, acol = (tid & 1) << 2;   // A tile: 128 rows x 8 k
    const int brow = tid >> 5, bcol = (tid & 31) << 2;  // B tile: 8 k x 128 cols
    const int tx   = tid & 15, ty = tid >> 4;           // 8x8 thread tile

    const float* Ab = A + (size_t)bm * 128 * K;
    const float* Bb = Wm + bn * 128;

    unsigned long long acc[8][4];
#pragma unroll
    for (int i = 0; i < 8; i++)
#pragma unroll
        for (int j = 0; j < 4; j++) acc[i][j] = 0ull;

    for (int kk = 0; kk < K; kk += 8) {
        float4 av = *(const float4*)(Ab + (size_t)arow * K + kk + acol);
        float4 bv = *(const float4*)(Bb + (size_t)(kk + brow) * N + bcol);
        __syncthreads();   // previous compute done before smem overwrite
        As[acol + 0][arow] = av.x;
        As[acol + 1][arow] = av.y;
        As[acol + 2][arow] = av.z;
        As[acol + 3][arow] = av.w;
        *(float4*)&Bs[brow][bcol] = bv;
        __syncthreads();
#pragma unroll
        for (int k = 0; k < 8; k++) {
            float4 a0 = *(const float4*)&As[k][ty * 8];
            float4 a1 = *(const float4*)&As[k][ty * 8 + 4];
            ulonglong2 b0 = *(const ulonglong2*)&Bs[k][tx * 8];
            ulonglong2 b1 = *(const ulonglong2*)&Bs[k][tx * 8 + 4];
            float ar[8] = {a0.x, a0.y, a0.z, a0.w, a1.x, a1.y, a1.z, a1.w};
            unsigned long long br[4] = {b0.x, b0.y, b1.x, b1.y};
#pragma unroll
            for (int i = 0; i < 8; i++) {
                unsigned long long ad;
                unsigned int au = __float_as_uint(ar[i]);
                asm("mov.b64 %0, {%1, %1};" : "=l"(ad) : "r"(au));
#pragma unroll
                for (int j = 0; j < 4; j++)
                    asm("fma.rn.f32x2 %0, %1, %2, %0;"
                        : "+l"(acc[i][j]) : "l"(ad), "l"(br[j]));
            }
        }
    }

    const int cb = bn * 128 + tx * 8;
    ulonglong2 bb0 = *(const ulonglong2*)&bias[cb];
    ulonglong2 bb1 = *(const ulonglong2*)&bias[cb + 4];
    unsigned long long bz[4] = {bb0.x, bb0.y, bb1.x, bb1.y};
#pragma unroll
    for (int i = 0; i < 8; i++) {
        size_t row = (size_t)bm * 128 + ty * 8 + i;
        float* Crow = C + row * N + cb;
#pragma unroll
        for (int j = 0; j < 4; j++) {
            unsigned long long v;
            asm("add.rn.f32x2 %0, %1, %2;" : "=l"(v) : "l"(acc[i][j]), "l"(bz[j]));
            *(unsigned long long*)(Crow + 2 * j) = v;
        }
    }
}

// ============================================================
// fast tanh: 1 - 2/(exp(2x)+1), MUFU EX2 + RCP.
// Saturates correctly for |x| large; abs err ~1e-7.
// ============================================================
__device__ __forceinline__ float fast_tanh(float x) {
    float e;
    asm("ex2.approx.f32 %0, %1;" : "=f"(e) : "f"(x * 2.8853900817779268f));
    float r;
    asm("rcp.approx.f32 %0, %1;" : "=f"(r) : "f"(e + 1.0f));
    return fmaf(-2.0f, r, 1.0f);
}

// ============================================================
// Phase 2: persistent cluster RNN scan.
// 16 clusters x 8 CTAs (grid 128), 256 threads/CTA.
// Cluster owns 4 batch rows; CTA rank r owns U columns [64r,64r+64)
// in registers (4-way K-split x 64 cols x 128 regs).
// Per step: FMA partials -> smem reduce -> 128-thread epilogue
// (fast tanh, DSMEM broadcast v2) -> cluster arrive -> hidden STG +
// next-xw prefetch -> cluster wait.
// ============================================================
__global__ void __launch_bounds__(256, 1) __cluster_dims__(8, 1, 1)
rnn_scan(const float* __restrict__ U,      // [512,512] row-major [k][h]
         float* __restrict__ hidden,       // [B,S,H]: in = xW+b, out = h
         float* __restrict__ hlast)        // [B,H]
{
    __shared__ float hbuf[2][512][4];      // [buf][k][batch]  (8 KB each)
    __shared__ float red[4][64][4];        // [ksplit][col][batch]

    const int tid = threadIdx.x;
    unsigned int rank;
    asm("mov.u32 %0, %%cluster_ctarank;" : "=r"(rank));
    const int cid = blockIdx.x >> 3;       // cluster id 0..15
    const int b0  = cid * 4;               // 4 batches per cluster
    const int ks  = tid >> 6;              // K split 0..3 (128 k each)
    const int c   = tid & 63;              // local column
    const int cg  = (int)rank * 64 + c;    // global column 0..511

    // One-time: U column-chunk into registers.
    float Ureg[128];
#pragma unroll
    for (int j = 0; j < 128; j++)
        Ureg[j] = U[(size_t)(ks * 128 + j) * Hsz + cg];

    // Epilogue mapping: tid<128, ecol = column, ebp = batch pair (0/1).
    const int ecol = tid & 63;
    const int ebp  = (tid >> 6) & 1;
    const int egc  = (int)rank * 64 + ecol;   // global column for epilogue

    // Precompute DSMEM target addresses for buffer 0 (parity adds 8192B).
    unsigned int ra[8];
    if (tid < 128) {
        unsigned int la =
            (unsigned int)__cvta_generic_to_shared(&hbuf[0][egc][2 * ebp]);
#pragma unroll
        for (int r = 0; r < 8; r++)
            asm("mapa.shared::cluster.u32 %0, %1, %2;"
                : "=r"(ra[r]) : "r"(la), "r"(r));
    }

    // h0 = 0 (both buffers)
    {
        float* hz = &hbuf[0][0][0];
        for (int i = tid; i < 2 * 512 * 4; i += 256) hz[i] = 0.0f;
    }
    __syncthreads();
    asm volatile("barrier.cluster.arrive.aligned;" ::: "memory");
    asm volatile("barrier.cluster.wait.aligned;" ::: "memory");

    // Prefetch xw for t=0 (two batches per epilogue thread).
    float xa = 0.f, xb = 0.f;
    size_t gaddr = 0;
    if (tid < 128) {
        gaddr = ((size_t)(b0 + 2 * ebp) * Ssz) * Hsz + egc;
        xa = __ldg(hidden + gaddr);
        xb = __ldg(hidden + gaddr + (size_t)Ssz * Hsz);
    }

    for (int t = 0; t < Ssz; t++) {
        const int p = t & 1;

        // ---- partial dot products: 4 batches x 1 col x 128 k (f32x2) ----
        const ulonglong2* hk =
            ((const ulonglong2*)&hbuf[p][0][0]) + (ks << 7);
        unsigned long long a01a = 0ull, a01b = 0ull, a23a = 0ull, a23b = 0ull;
#pragma unroll
        for (int j = 0; j < 128; j += 2) {
            ulonglong2 h0 = hk[j];
            ulonglong2 h1 = hk[j + 1];
            unsigned long long u0, u1;
            unsigned int uu0 = __float_as_uint(Ureg[j]);
            unsigned int uu1 = __float_as_uint(Ureg[j + 1]);
            asm("mov.b64 %0, {%1, %1};" : "=l"(u0) : "r"(uu0));
            asm("mov.b64 %0, {%1, %1};" : "=l"(u1) : "r"(uu1));
            asm("fma.rn.f32x2 %0, %1, %2, %0;" : "+l"(a01a) : "l"(u0), "l"(h0.x));
            asm("fma.rn.f32x2 %0, %1, %2, %0;" : "+l"(a23a) : "l"(u0), "l"(h0.y));
            asm("fma.rn.f32x2 %0, %1, %2, %0;" : "+l"(a01b) : "l"(u1), "l"(h1.x));
            asm("fma.rn.f32x2 %0, %1, %2, %0;" : "+l"(a23b) : "l"(u1), "l"(h1.y));
        }
        unsigned long long a01, a23;
        asm("add.rn.f32x2 %0, %1, %2;" : "=l"(a01) : "l"(a01a), "l"(a01b));
        asm("add.rn.f32x2 %0, %1, %2;" : "=l"(a23) : "l"(a23a), "l"(a23b));
        unsigned int w0, w1, w2, w3;
        asm("mov.b64 {%0, %1}, %2;" : "=r"(w0), "=r"(w1) : "l"(a01));
        asm("mov.b64 {%0, %1}, %2;" : "=r"(w2), "=r"(w3) : "l"(a23));
        *(float4*)&red[ks][c][0] =
            make_float4(__uint_as_float(w0), __uint_as_float(w1),
                        __uint_as_float(w2), __uint_as_float(w3));
        __syncthreads();

        // ---- epilogue across 128 threads (2 values each) ----
        float v0 = 0.f, v1 = 0.f;
        if (tid < 128) {
            float2 r0 = *(const float2*)&red[0][ecol][2 * ebp];
            float2 r1 = *(const float2*)&red[1][ecol][2 * ebp];
            float2 r2 = *(const float2*)&red[2][ecol][2 * ebp];
            float2 r3 = *(const float2*)&red[3][ecol][2 * ebp];
            v0 = fast_tanh(xa + r0.x + r1.x + r2.x + r3.x);
            v1 = fast_tanh(xb + r0.y + r1.y + r2.y + r3.y);

            // DSMEM broadcast into hbuf[p^1] of all 8 cluster CTAs.
            const unsigned int off = (unsigned int)(p ^ 1) * 8192u;
#pragma unroll
            for (int r = 0; r < 8; r++)
                asm volatile("st.shared::cluster.v2.f32 [%0], {%1, %2};"
                             :: "r"(ra[r] + off), "f"(v0), "f"(v1)
                             : "memory");
        }

        // Release our DSMEM writes; overlap the wait with global traffic.
        asm volatile("barrier.cluster.arrive.aligned;" ::: "memory");

        if (tid < 128) {
            hidden[gaddr]                    = v0;  // overwrite xw[t] in place
            hidden[gaddr + (size_t)Ssz * Hsz] = v1;
            if (t == Ssz - 1) {
                const size_t lb = (size_t)(b0 + 2 * ebp) * Hsz + egc;
                hlast[lb]       = v0;
                hlast[lb + Hsz] = v1;
            } else {
                gaddr += Hsz;                       // advance to t+1
                xa = __ldg(hidden + gaddr);         // prefetch next xw
                xb = __ldg(hidden + gaddr + (size_t)Ssz * Hsz);
            }
        }

        asm volatile("barrier.cluster.wait.aligned;" ::: "memory");
    }
}

extern "C" void kernel_launch(void* const* d_in, const int* in_sizes, int n_in,
                              void* d_out, int out_size) {
    const float* x  = (const float*)d_in[0];   // [64,2048,512]
    const float* Wi = (const float*)d_in[1];   // [512,512]
    const float* Ui = (const float*)d_in[2];   // [512,512]
    const float* bi = (const float*)d_in[3];   // [512]

    float* hidden = (float*)d_out;                        // [B,S,H]
    float* hlast  = hidden + (size_t)Bsz * Ssz * Hsz;     // [B,H]

    // Phase 1: xW + b -> hidden (in-place staging)
    dim3 g1(Hsz / 128, (Bsz * Ssz) / 128);   // (4, 1024)
    sgemm_xw<<<g1, 256>>>(x, Wi, bi, hidden);

    // Phase 2: sequential scan, persistent cluster kernel.
    rnn_scan<<<128, 256>>>(Ui, hidden, hlast);
}